// round 17
// baseline (speedup 1.0000x reference)
#include <cuda_runtime.h>
#include <cuda_fp16.h>
#include <cstdint>

#define NN  50000     // num nodes
#define EE  800000    // num edges
#define CC  64        // channels (in == out)
#define CAP 96        // per-node slot capacity (Poisson(16): P(deg>96) ~ 1e-50)
#define OVF_MAX 8192  // overflow edge buffer (correctness fallback)
#define PAD 8         // counter padding stride (32 B) to spread LTS atomic hash

// ---------------- scratch (no allocations; zero-initialized at module load) ----
__device__ __align__(256) int    g_cntp[NN * PAD];   // padded degree/cursor (1.6 MB)
__device__ __align__(256) float  g_dis[NN];          // clip(deg,1)^-1/2
__device__ __align__(256) __half g_xh[NN * CC];      // fp16 mirror of x (6.4 MB)
__device__ __align__(256) int    g_slot[NN * CAP];   // src lists per target (19.2 MB)
__device__ __align__(256) int    g_ovf[OVF_MAX * 2]; // overflow (src,tgt) pairs
__device__ __align__(256) float  g_agg[NN * CC];     // 12.8 MB aggregate
__device__ int g_novf;                               // overflow count

__device__ __forceinline__ int load_idx(const void* edges, int64_t pos, int is64) {
    if (is64) return (int)reinterpret_cast<const long long*>(edges)[pos];
    return reinterpret_cast<const int*>(edges)[pos];
}

// ---------------- kernel 1: fill slot table (inline dtype detect, 4 edges/thread) --
__global__ void k_fill(const void* __restrict__ edges, int E) {
    __shared__ int sflag;
    if (threadIdx.x == 0) sflag = 0;
    __syncthreads();
    if (threadIdx.x < 128) {
        const unsigned* w = reinterpret_cast<const unsigned*>(edges);
        int64_t p = 2 * (int64_t)threadIdx.x + 1;
        if (p < 2 * (int64_t)E && w[p] != 0u) atomicOr(&sflag, 1);
    }
    __syncthreads();
    int is64 = (sflag == 0);

    int64_t base = ((int64_t)blockIdx.x * blockDim.x + threadIdx.x) * 4;
    if (base >= E) return;

    int src[4], tgt[4];
    int nv = 0;
#pragma unroll
    for (int j = 0; j < 4; j++) {
        int64_t i = base + j;
        if (i < E) {
            src[j] = load_idx(edges, i, is64);
            tgt[j] = load_idx(edges, (int64_t)E + i, is64);
            nv = j + 1;
        }
    }
    int pos[4];
#pragma unroll
    for (int j = 0; j < 4; j++)
        if (j < nv) pos[j] = atomicAdd(&g_cntp[tgt[j] * PAD], 1);
#pragma unroll
    for (int j = 0; j < 4; j++) {
        if (j < nv) {
            if (pos[j] < CAP) {
                g_slot[(int64_t)tgt[j] * CAP + pos[j]] = src[j];
            } else {
                int o = atomicAdd(&g_novf, 1);
                if (o < OVF_MAX) { g_ovf[2 * o] = src[j]; g_ovf[2 * o + 1] = tgt[j]; }
            }
        }
    }
}

// ---------------- kernel 2: deg_inv_sqrt + fp16 mirror of x ----------------
__global__ void k_prep(const float* __restrict__ x, int n) {
    int i = blockIdx.x * blockDim.x + threadIdx.x;
    if (i < n) g_dis[i] = rsqrtf(fmaxf((float)g_cntp[i * PAD], 1.0f));

    const float2* x2 = reinterpret_cast<const float2*>(x);
    __half2* xh2 = reinterpret_cast<__half2*>(g_xh);
    int total = n * (CC / 2);
    int stride = gridDim.x * blockDim.x;
    for (int k = i; k < total; k += stride)
        xh2[k] = __float22half2_rn(x2[k]);
}

// ---------------- kernel 3: gather-aggregate (fp16 gathers, no atomics) ------
__global__ __launch_bounds__(256) void k_agg(const float* __restrict__ x, int n) {
    int t  = blockIdx.x * blockDim.x + threadIdx.x;
    int nd = t >> 4;
    int q  = threadIdx.x & 15;
    if (nd >= n) return;

    int deg = g_cntp[nd * PAD];
    int d   = deg < CAP ? deg : CAP;
    float dt = g_dis[nd];
    const int* slots = g_slot + (int64_t)nd * CAP;
    const uint2* xh = reinterpret_cast<const uint2*>(g_xh);

    float4 acc = make_float4(0.f, 0.f, 0.f, 0.f);
    int e = 0;
    for (; e + 4 <= d; e += 4) {
        int s0 = slots[e + 0], s1 = slots[e + 1], s2 = slots[e + 2], s3 = slots[e + 3];
        float n0 = __ldg(&g_dis[s0]) * dt;
        float n1 = __ldg(&g_dis[s1]) * dt;
        float n2 = __ldg(&g_dis[s2]) * dt;
        float n3 = __ldg(&g_dis[s3]) * dt;
        uint2 r0 = __ldg(&xh[(int64_t)s0 * 16 + q]);
        uint2 r1 = __ldg(&xh[(int64_t)s1 * 16 + q]);
        uint2 r2 = __ldg(&xh[(int64_t)s2 * 16 + q]);
        uint2 r3 = __ldg(&xh[(int64_t)s3 * 16 + q]);
        {
            float2 fa = __half22float2(*reinterpret_cast<__half2*>(&r0.x));
            float2 fb = __half22float2(*reinterpret_cast<__half2*>(&r0.y));
            acc.x += fa.x * n0; acc.y += fa.y * n0; acc.z += fb.x * n0; acc.w += fb.y * n0;
        }
        {
            float2 fa = __half22float2(*reinterpret_cast<__half2*>(&r1.x));
            float2 fb = __half22float2(*reinterpret_cast<__half2*>(&r1.y));
            acc.x += fa.x * n1; acc.y += fa.y * n1; acc.z += fb.x * n1; acc.w += fb.y * n1;
        }
        {
            float2 fa = __half22float2(*reinterpret_cast<__half2*>(&r2.x));
            float2 fb = __half22float2(*reinterpret_cast<__half2*>(&r2.y));
            acc.x += fa.x * n2; acc.y += fa.y * n2; acc.z += fb.x * n2; acc.w += fb.y * n2;
        }
        {
            float2 fa = __half22float2(*reinterpret_cast<__half2*>(&r3.x));
            float2 fb = __half22float2(*reinterpret_cast<__half2*>(&r3.y));
            acc.x += fa.x * n3; acc.y += fa.y * n3; acc.z += fb.x * n3; acc.w += fb.y * n3;
        }
    }
    for (; e < d; e++) {
        int s = slots[e];
        float nm = __ldg(&g_dis[s]) * dt;
        uint2 r = __ldg(&xh[(int64_t)s * 16 + q]);
        float2 fa = __half22float2(*reinterpret_cast<__half2*>(&r.x));
        float2 fb = __half22float2(*reinterpret_cast<__half2*>(&r.y));
        acc.x += fa.x * nm; acc.y += fa.y * nm; acc.z += fb.x * nm; acc.w += fb.y * nm;
    }

    int novf = g_novf;
    if (novf > 0) {
        int ne = novf < OVF_MAX ? novf : OVF_MAX;
        const float4* x4 = reinterpret_cast<const float4*>(x);
        for (int o = 0; o < ne; o++) {
            if (g_ovf[2 * o + 1] == nd) {
                int s = g_ovf[2 * o];
                float nm = g_dis[s] * dt;
                float4 v = __ldg(&x4[(int64_t)s * 16 + q]);
                acc.x += v.x * nm; acc.y += v.y * nm; acc.z += v.z * nm; acc.w += v.w * nm;
            }
        }
    }

    reinterpret_cast<float4*>(g_agg)[(int64_t)nd * 16 + q] = acc;
}

// ---------------- kernel 4: out = relu(agg @ W^T + b), FFMA2 streaming -------
// 2 threads per node: thread h in {0,1} computes outputs [h*32, h*32+32) as
// 16 packed f32x2 accumulators. a streamed (16 LDG.128), W pair-packed in smem
// read as ulonglong2 (warp-uniform -> broadcast LDS, conflict-free).
// Block 256 thr = 128 nodes; warp-uniform h via tid>>7.
__global__ __launch_bounds__(256) void k_gemm(const float* __restrict__ W,
                                              const float* __restrict__ b,
                                              float* __restrict__ out, int n) {
    // Reset per-invocation state for the NEXT run (globals start zeroed at load).
    int tix = blockIdx.x * blockDim.x + threadIdx.x;
    if (tix < NN) g_cntp[tix * PAD] = 0;
    if (tix == 0) g_novf = 0;

    __shared__ __align__(16) unsigned long long Wp[64 * 32];  // [c][pair] 16 KB
    __shared__ unsigned long long bp[32];

    for (int idx = threadIdx.x; idx < 64 * 32; idx += 256) {
        int c = idx >> 5, p = idx & 31;
        unsigned long long v;
        asm("mov.b64 %0, {%1, %2};" : "=l"(v)
            : "f"(W[(2 * p) * CC + c]), "f"(W[(2 * p + 1) * CC + c]));
        Wp[idx] = v;
    }
    if (threadIdx.x < 32) {
        unsigned long long v;
        asm("mov.b64 %0, {%1, %2};" : "=l"(v)
            : "f"(b[2 * threadIdx.x]), "f"(b[2 * threadIdx.x + 1]));
        bp[threadIdx.x] = v;
    }
    __syncthreads();

    int nd = blockIdx.x * 128 + (threadIdx.x & 127);
    int h  = threadIdx.x >> 7;              // warp-uniform
    if (nd >= n) return;

    unsigned long long acc[16];
#pragma unroll
    for (int k = 0; k < 16; k++) acc[k] = bp[h * 16 + k];

    const float4* arow = reinterpret_cast<const float4*>(g_agg + (int64_t)nd * CC);
#pragma unroll
    for (int c4 = 0; c4 < 16; c4++) {
        float4 av = __ldg(arow + c4);
        float ac[4] = {av.x, av.y, av.z, av.w};
#pragma unroll
        for (int cc = 0; cc < 4; cc++) {
            unsigned long long a2;
            asm("mov.b64 %0, {%1, %1};" : "=l"(a2) : "f"(ac[cc]));
            const ulonglong2* w2 = reinterpret_cast<const ulonglong2*>(
                &Wp[(c4 * 4 + cc) * 32 + h * 16]);
#pragma unroll
            for (int pp = 0; pp < 8; pp++) {
                ulonglong2 wv = w2[pp];
                asm("fma.rn.f32x2 %0, %1, %2, %0;" : "+l"(acc[2 * pp])     : "l"(a2), "l"(wv.x));
                asm("fma.rn.f32x2 %0, %1, %2, %0;" : "+l"(acc[2 * pp + 1]) : "l"(a2), "l"(wv.y));
            }
        }
    }

    float4* orow = reinterpret_cast<float4*>(out + (int64_t)nd * CC + h * 32);
#pragma unroll
    for (int k2 = 0; k2 < 8; k2++) {
        float l0, h0, l1, h1;
        asm("mov.b64 {%0, %1}, %2;" : "=f"(l0), "=f"(h0) : "l"(acc[2 * k2]));
        asm("mov.b64 {%0, %1}, %2;" : "=f"(l1), "=f"(h1) : "l"(acc[2 * k2 + 1]));
        orow[k2] = make_float4(fmaxf(l0, 0.f), fmaxf(h0, 0.f),
                               fmaxf(l1, 0.f), fmaxf(h1, 0.f));
    }
}

// ---------------- launch (4 kernels) ----------------
extern "C" void kernel_launch(void* const* d_in, const int* in_sizes, int n_in,
                              void* d_out, int out_size) {
    const float* x     = (const float*)d_in[0];
    const void*  edges = d_in[1];                 // int32 or int64, runtime-detected
    const float* W     = (const float*)d_in[2];
    const float* b     = (const float*)d_in[3];
    float* out = (float*)d_out;

    const int n = in_sizes[0] / CC;               // 50000
    const int E = in_sizes[1] / 2;                // 800000

    k_fill<<<(E + 1023) / 1024, 256>>>(edges, E);
    k_prep<<<(n * (CC / 2) + 255) / 256, 256>>>(x, n);
    {
        int64_t threads = (int64_t)n * 16;
        int blocks = (int)((threads + 255) / 256);
        k_agg<<<blocks, 256>>>(x, n);
    }
    k_gemm<<<(n + 127) / 128, 256>>>(W, b, out, n);
}